// round 4
// baseline (speedup 1.0000x reference)
#include <cuda_runtime.h>
#include <math.h>

#define BB 8
#define LL 8192
#define CCH 256
#define NN 512
#define KK 16
#define FMINF 1.17549435e-38f

// scratch (no allocations allowed)
__device__ float g_w[BB * NN];    // FTZ proto_weights
__device__ float g_t[BB * NN];    // log(w), -inf where 0
__device__ float g_pn2[NN];       // |p_n|^2
__device__ float g_qq[BB * LL];   // |q_l|^2

__device__ __forceinline__ float warp_maxf(float v) {
    #pragma unroll
    for (int o = 16; o; o >>= 1) v = fmaxf(v, __shfl_xor_sync(0xffffffffu, v, o));
    return v;
}
__device__ __forceinline__ float warp_sumf(float v) {
    #pragma unroll
    for (int o = 16; o; o >>= 1) v += __shfl_xor_sync(0xffffffffu, v, o);
    return v;
}
__device__ __forceinline__ double warp_sumd(double v) {
    #pragma unroll
    for (int o = 16; o; o >>= 1) v += __shfl_xor_sync(0xffffffffu, v, o);
    return v;
}

// ---------------------------------------------------------------------------
// Per-batch proto weights, FTZ semantics:
//   e = expf(x - xmax) flushed; Zw = f32(sum e); w = e/Zw flushed.
// ---------------------------------------------------------------------------
__global__ void prep_w_kernel(const float* __restrict__ P,
                              const float* __restrict__ gt) {
    int b = blockIdx.x;
    int tid = threadIdx.x;
    __shared__ float gs[CCH];
    __shared__ float xs[NN];
    __shared__ float redf[256];
    __shared__ double redd[256];
    __shared__ float sXmax, sZw;

    if (tid < CCH) {
        double s = 0.0;
        #pragma unroll
        for (int k = 0; k < KK; k++) s += (double)gt[(b * KK + k) * CCH + tid];
        gs[tid] = __fdiv_rn((float)s, 16.0f);
    }
    __syncthreads();

    for (int n = tid; n < NN; n += blockDim.x) {
        double a = 0.0;
        const float* pr = P + n * CCH;
        for (int c = 0; c < CCH; c++) a = fma((double)gs[c], (double)pr[c], a);
        xs[n] = __fdiv_rn((float)a, 0.1f);
    }
    __syncthreads();

    {   // block max
        float m = -INFINITY;
        for (int n = tid; n < NN; n += blockDim.x) m = fmaxf(m, xs[n]);
        redf[tid] = m;
        __syncthreads();
        for (int s = 128; s; s >>= 1) {
            if (tid < s) redf[tid] = fmaxf(redf[tid], redf[tid + s]);
            __syncthreads();
        }
        if (tid == 0) sXmax = redf[0];
        __syncthreads();
    }
    float X = sXmax;

    {   // Zw = f32(sum of flushed exps)
        double z = 0.0;
        for (int n = tid; n < NN; n += blockDim.x) {
            float e = expf(__fsub_rn(xs[n], X));
            if (e >= FMINF) z += (double)e;
        }
        redd[tid] = z;
        __syncthreads();
        for (int s = 128; s; s >>= 1) {
            if (tid < s) redd[tid] += redd[tid + s];
            __syncthreads();
        }
        if (tid == 0) sZw = (float)redd[0];
        __syncthreads();
    }
    float Zw = sZw;

    for (int n = tid; n < NN; n += blockDim.x) {
        float e = expf(__fsub_rn(xs[n], X));
        if (e < FMINF) e = 0.f;
        float w = __fdiv_rn(e, Zw);
        if (w < FMINF) w = 0.f;
        g_w[b * NN + n] = w;
        g_t[b * NN + n] = (w > 0.f) ? logf(w) : -INFINITY;
    }
}

__global__ void prep_pn2_kernel(const float* __restrict__ P) {
    int n = blockIdx.x * blockDim.x + threadIdx.x;
    if (n < NN) {
        float s = 0.f;
        const float* pr = P + n * CCH;
        for (int c = 0; c < CCH; c++) s = fmaf(pr[c], pr[c], s);
        g_pn2[n] = s;
    }
}

__global__ void prep_qq_kernel(const float* __restrict__ Q) {
    int wid = threadIdx.x >> 5, lane = threadIdx.x & 31;
    int row = blockIdx.x * 8 + wid;
    const float4* q4 = (const float4*)Q + (size_t)row * (CCH / 4);
    float4 a = q4[lane];
    float4 c = q4[lane + 32];
    float s = a.x * a.x + a.y * a.y + a.z * a.z + a.w * a.w
            + c.x * c.x + c.y * c.y + c.z * c.z + c.w * c.w;
    s = warp_sumf(s);
    if (lane == 0) g_qq[row] = s;
}

// ---------------------------------------------------------------------------
// Main kernel: 32 queries x 512 protos per block; warp owns 4 queries.
// Epilogue: FTZ f32 chain  e=expf(u) [flush] -> s=e/Za [flush] -> p=s*w [flush],
// argmax ascending-n strict '>', all-zero -> index 0.
// ---------------------------------------------------------------------------
__global__ void __launch_bounds__(256, 2)
match_kernel(const float* __restrict__ Q, const float* __restrict__ P,
             float* __restrict__ out) {
    __shared__ __align__(16) float p_s[16][NN];    // 32 KB
    __shared__ __align__(16) float q_s[16][32];    // 2 KB
    __shared__ float wS[NN], tS[NN], pn2S[NN];     // 6 KB

    int tid = threadIdx.x;
    int b = blockIdx.y;
    int l0 = blockIdx.x * 32;
    int lane = tid & 31, lg = tid >> 5;

    for (int i = tid; i < NN; i += 256) {
        wS[i] = g_w[b * NN + i];
        tS[i] = g_t[b * NN + i];
        pn2S[i] = g_pn2[i];
    }

    const float* Qb = Q + (size_t)(b * LL + l0) * CCH;

    float acc[4][16];
    #pragma unroll
    for (int i = 0; i < 4; i++)
        #pragma unroll
        for (int j = 0; j < 16; j++) acc[i][j] = 0.f;

    for (int cc = 0; cc < CCH; cc += 16) {
        #pragma unroll
        for (int r = 0; r < 8; r++) {
            int idx = tid + r * 256;
            int n = idx >> 2, f = idx & 3;
            float4 v = *(const float4*)(P + n * CCH + cc + f * 4);
            p_s[f * 4 + 0][n] = v.x;
            p_s[f * 4 + 1][n] = v.y;
            p_s[f * 4 + 2][n] = v.z;
            p_s[f * 4 + 3][n] = v.w;
        }
        if (tid < 128) {
            int l = tid >> 2, f = tid & 3;
            float4 v = *(const float4*)(Qb + l * CCH + cc + f * 4);
            q_s[f * 4 + 0][l] = v.x;
            q_s[f * 4 + 1][l] = v.y;
            q_s[f * 4 + 2][l] = v.z;
            q_s[f * 4 + 3][l] = v.w;
        }
        __syncthreads();
        #pragma unroll
        for (int c = 0; c < 16; c++) {
            float4 qv = *(const float4*)(&q_s[c][lg * 4]);
            #pragma unroll
            for (int j = 0; j < 16; j++) {
                float pv = p_s[c][lane + 32 * j];
                acc[0][j] = fmaf(qv.x, pv, acc[0][j]);
                acc[1][j] = fmaf(qv.y, pv, acc[1][j]);
                acc[2][j] = fmaf(qv.z, pv, acc[2][j]);
                acc[3][j] = fmaf(qv.w, pv, acc[3][j]);
            }
        }
        __syncthreads();
    }

    // ---- epilogue ----
    #pragma unroll 1
    for (int i = 0; i < 4; i++) {
        float dmax = acc[i][0];
        #pragma unroll
        for (int j = 1; j < 16; j++) dmax = fmaxf(dmax, acc[i][j]);
        dmax = warp_maxf(dmax);
        float Xf = __fdiv_rn(dmax, 0.1f);

        // Za = f32(sum of flushed exps); only u > -88 contributes
        double zs = 0.0;
        #pragma unroll
        for (int j = 0; j < 16; j++) {
            if (acc[i][j] > dmax - 8.8f) {
                float x = __fdiv_rn(acc[i][j], 0.1f);
                float e = expf(__fsub_rn(x, Xf));
                if (e >= FMINF) zs += (double)e;
            }
        }
        zs = warp_sumd(zs);
        float Za = (float)zs;

        // candidate keys: 10*(d - dmax) + log w  (ranking ~ log product)
        float key[16];
        float kmax = -INFINITY;
        #pragma unroll
        for (int j = 0; j < 16; j++) {
            key[j] = fmaf(acc[i][j] - dmax, 10.0f, tS[lane + 32 * j]);
            kmax = fmaxf(kmax, key[j]);
        }
        kmax = warp_maxf(kmax);

        int bn = 0;
        float bp = 0.f;
        float bd = __shfl_sync(0xffffffffu, acc[i][0], 0);  // dot(n=0) fallback

        if (kmax >= -87.4f) {
            float thr = kmax - 0.02f;
            #pragma unroll 1
            for (int j = 0; j < 16; j++) {
                unsigned msk = __ballot_sync(0xffffffffu, key[j] >= thr);
                while (msk) {
                    int ln = __ffs(msk) - 1;
                    msk &= msk - 1;
                    int n = ln + 32 * j;
                    float Ac = __shfl_sync(0xffffffffu, acc[i][j], ln);
                    float x = __fdiv_rn(Ac, 0.1f);
                    float e = expf(__fsub_rn(x, Xf));
                    if (e < FMINF) e = 0.f;
                    float s = __fdiv_rn(e, Za);
                    if (s < FMINF) s = 0.f;
                    float p = __fmul_rn(s, wS[n]);
                    if (p < FMINF) p = 0.f;
                    if (p > bp) { bp = p; bn = n; bd = Ac; }  // ascending n: first tie wins
                }
            }
        }

        if (lane == 0) {
            int l = l0 + lg * 4 + i;
            float rd = fmaf(-2.0f, bd, g_qq[(size_t)b * LL + l]) + pn2S[bn];
            out[(size_t)b * LL + l] = rd;
        }
    }
}

// ---------------------------------------------------------------------------
extern "C" void kernel_launch(void* const* d_in, const int* in_sizes, int n_in,
                              void* d_out, int out_size) {
    const float* Q = nullptr;
    const float* P = nullptr;
    const float* G = nullptr;
    for (int i = 0; i < n_in; i++) {
        if (in_sizes[i] == BB * LL * CCH) Q = (const float*)d_in[i];
        else if (in_sizes[i] == NN * CCH) P = (const float*)d_in[i];
        else if (in_sizes[i] == BB * KK * CCH) G = (const float*)d_in[i];
    }
    float* out = (float*)d_out;

    prep_w_kernel<<<BB, 256>>>(P, G);
    prep_pn2_kernel<<<2, 256>>>(P);
    prep_qq_kernel<<<BB * LL / 8, 256>>>(Q);
    dim3 grid(LL / 32, BB);
    match_kernel<<<grid, 256>>>(Q, P, out);
}

// round 5
// speedup vs baseline: 1.3244x; 1.3244x over previous
#include <cuda_runtime.h>
#include <math.h>

#define BB 8
#define LL 8192
#define CCH 256
#define NN 512
#define KK 16
#define FMINF 1.17549435e-38f

// scratch (no allocations allowed)
__device__ float g_w[BB * NN];    // FTZ proto_weights
__device__ float g_t[BB * NN];    // log(w), -inf where 0
__device__ float g_pn2[NN];       // |p_n|^2
__device__ float g_qq[BB * LL];   // |q_l|^2

__device__ __forceinline__ float warp_maxf(float v) {
    #pragma unroll
    for (int o = 16; o; o >>= 1) v = fmaxf(v, __shfl_xor_sync(0xffffffffu, v, o));
    return v;
}
__device__ __forceinline__ float warp_sumf(float v) {
    #pragma unroll
    for (int o = 16; o; o >>= 1) v += __shfl_xor_sync(0xffffffffu, v, o);
    return v;
}
__device__ __forceinline__ double warp_sumd(double v) {
    #pragma unroll
    for (int o = 16; o; o >>= 1) v += __shfl_xor_sync(0xffffffffu, v, o);
    return v;
}

// ---- packed f32x2 helpers (Blackwell FFMA2) ----
__device__ __forceinline__ void ffma2(unsigned long long& d,
                                      unsigned long long a,
                                      unsigned long long b) {
    asm("fma.rn.f32x2 %0, %1, %2, %0;" : "+l"(d) : "l"(a), "l"(b));
}
__device__ __forceinline__ unsigned long long pack2(float x) {
    unsigned long long r;
    asm("mov.b64 %0, {%1, %1};" : "=l"(r) : "f"(x));
    return r;
}
__device__ __forceinline__ void unpack2(unsigned long long v, float& lo, float& hi) {
    asm("mov.b64 {%0, %1}, %2;" : "=f"(lo), "=f"(hi) : "l"(v));
}

// ---------------------------------------------------------------------------
// Per-batch proto weights, FTZ semantics (warp-per-n coalesced dot phase).
// ---------------------------------------------------------------------------
__global__ void prep_w_kernel(const float* __restrict__ P,
                              const float* __restrict__ gt) {
    int b = blockIdx.x;
    int tid = threadIdx.x;
    int lane = tid & 31, wid = tid >> 5;
    __shared__ double gsd[CCH];
    __shared__ float xs[NN];
    __shared__ float redf[256];
    __shared__ double redd[256];
    __shared__ float sXmax, sZw;

    if (tid < CCH) {
        double s = 0.0;
        #pragma unroll
        for (int k = 0; k < KK; k++) s += (double)gt[(b * KK + k) * CCH + tid];
        gsd[tid] = (double)__fdiv_rn((float)s, 16.0f);
    }
    __syncthreads();

    // warp per n, coalesced: lane covers c = lane*4..+3 and 128+lane*4..+3
    for (int n = wid; n < NN; n += 8) {
        const float4* pr4 = (const float4*)(P + n * CCH);
        float4 v0 = pr4[lane];
        float4 v1 = pr4[lane + 32];
        int c0 = lane * 4, c1 = 128 + lane * 4;
        double a = 0.0;
        a = fma((double)v0.x, gsd[c0 + 0], a);
        a = fma((double)v0.y, gsd[c0 + 1], a);
        a = fma((double)v0.z, gsd[c0 + 2], a);
        a = fma((double)v0.w, gsd[c0 + 3], a);
        a = fma((double)v1.x, gsd[c1 + 0], a);
        a = fma((double)v1.y, gsd[c1 + 1], a);
        a = fma((double)v1.z, gsd[c1 + 2], a);
        a = fma((double)v1.w, gsd[c1 + 3], a);
        a = warp_sumd(a);
        if (lane == 0) xs[n] = __fdiv_rn((float)a, 0.1f);
    }
    __syncthreads();

    {   // block max
        float m = -INFINITY;
        for (int n = tid; n < NN; n += blockDim.x) m = fmaxf(m, xs[n]);
        redf[tid] = m;
        __syncthreads();
        for (int s = 128; s; s >>= 1) {
            if (tid < s) redf[tid] = fmaxf(redf[tid], redf[tid + s]);
            __syncthreads();
        }
        if (tid == 0) sXmax = redf[0];
        __syncthreads();
    }
    float X = sXmax;

    {   // Zw = f32(sum of flushed exps)
        double z = 0.0;
        for (int n = tid; n < NN; n += blockDim.x) {
            float e = expf(__fsub_rn(xs[n], X));
            if (e >= FMINF) z += (double)e;
        }
        redd[tid] = z;
        __syncthreads();
        for (int s = 128; s; s >>= 1) {
            if (tid < s) redd[tid] += redd[tid + s];
            __syncthreads();
        }
        if (tid == 0) sZw = (float)redd[0];
        __syncthreads();
    }
    float Zw = sZw;

    for (int n = tid; n < NN; n += blockDim.x) {
        float e = expf(__fsub_rn(xs[n], X));
        if (e < FMINF) e = 0.f;
        float w = __fdiv_rn(e, Zw);
        if (w < FMINF) w = 0.f;
        g_w[b * NN + n] = w;
        g_t[b * NN + n] = (w > 0.f) ? logf(w) : -INFINITY;
    }
}

// warp per n, coalesced
__global__ void prep_pn2_kernel(const float* __restrict__ P) {
    int lane = threadIdx.x & 31, wid = threadIdx.x >> 5;
    int n = blockIdx.x * 8 + wid;
    const float4* pr4 = (const float4*)(P + n * CCH);
    float4 a = pr4[lane];
    float4 c = pr4[lane + 32];
    float s = a.x * a.x + a.y * a.y + a.z * a.z + a.w * a.w
            + c.x * c.x + c.y * c.y + c.z * c.z + c.w * c.w;
    s = warp_sumf(s);
    if (lane == 0) g_pn2[n] = s;
}

__global__ void prep_qq_kernel(const float* __restrict__ Q) {
    int wid = threadIdx.x >> 5, lane = threadIdx.x & 31;
    int row = blockIdx.x * 8 + wid;
    const float4* q4 = (const float4*)Q + (size_t)row * (CCH / 4);
    float4 a = q4[lane];
    float4 c = q4[lane + 32];
    float s = a.x * a.x + a.y * a.y + a.z * a.z + a.w * a.w
            + c.x * c.x + c.y * c.y + c.z * c.z + c.w * c.w;
    s = warp_sumf(s);
    if (lane == 0) g_qq[row] = s;
}

// ---------------------------------------------------------------------------
// Main kernel: 32 queries x 512 protos per block; warp owns 4 queries.
// FFMA2 (f32x2) mainloop; thread n-tile: n = jq*128 + lane*4 + k, jq<4, k<4.
// Epilogue: FTZ chain identical to round-4 semantics (bit-identical accs).
// ---------------------------------------------------------------------------
__global__ void __launch_bounds__(256, 2)
match_kernel(const float* __restrict__ Q, const float* __restrict__ P,
             float* __restrict__ out) {
    __shared__ __align__(16) float p_s[16][516];   // padded rows (33 KB)
    __shared__ __align__(16) float q_s[16][36];    // padded rows (2.3 KB)
    __shared__ float wS[NN], tS[NN], pn2S[NN];     // 6 KB

    int tid = threadIdx.x;
    int b = blockIdx.y;
    int l0 = blockIdx.x * 32;
    int lane = tid & 31, lg = tid >> 5;

    for (int i = tid; i < NN; i += 256) {
        wS[i] = g_w[b * NN + i];
        tS[i] = g_t[b * NN + i];
        pn2S[i] = g_pn2[i];
    }

    const float* Qb = Q + (size_t)(b * LL + l0) * CCH;

    unsigned long long acc2[4][8];
    #pragma unroll
    for (int i = 0; i < 4; i++)
        #pragma unroll
        for (int m = 0; m < 8; m++) acc2[i][m] = 0ULL;   // two +0.0f

    for (int cc = 0; cc < CCH; cc += 16) {
        #pragma unroll
        for (int r = 0; r < 8; r++) {
            int idx = tid + r * 256;
            int n = idx >> 2, f = idx & 3;
            float4 v = *(const float4*)(P + n * CCH + cc + f * 4);
            p_s[f * 4 + 0][n] = v.x;
            p_s[f * 4 + 1][n] = v.y;
            p_s[f * 4 + 2][n] = v.z;
            p_s[f * 4 + 3][n] = v.w;
        }
        if (tid < 128) {
            int l = tid >> 2, f = tid & 3;
            float4 v = *(const float4*)(Qb + l * CCH + cc + f * 4);
            q_s[f * 4 + 0][l] = v.x;
            q_s[f * 4 + 1][l] = v.y;
            q_s[f * 4 + 2][l] = v.z;
            q_s[f * 4 + 3][l] = v.w;
        }
        __syncthreads();
        #pragma unroll
        for (int c = 0; c < 16; c++) {
            float4 qv = *(const float4*)(&q_s[c][lg * 4]);
            unsigned long long qd0 = pack2(qv.x);
            unsigned long long qd1 = pack2(qv.y);
            unsigned long long qd2 = pack2(qv.z);
            unsigned long long qd3 = pack2(qv.w);
            ulonglong2 pA = *(const ulonglong2*)(&p_s[c][0 + lane * 4]);
            ulonglong2 pB = *(const ulonglong2*)(&p_s[c][128 + lane * 4]);
            ulonglong2 pC = *(const ulonglong2*)(&p_s[c][256 + lane * 4]);
            ulonglong2 pD = *(const ulonglong2*)(&p_s[c][384 + lane * 4]);
            ffma2(acc2[0][0], qd0, pA.x); ffma2(acc2[0][1], qd0, pA.y);
            ffma2(acc2[0][2], qd0, pB.x); ffma2(acc2[0][3], qd0, pB.y);
            ffma2(acc2[0][4], qd0, pC.x); ffma2(acc2[0][5], qd0, pC.y);
            ffma2(acc2[0][6], qd0, pD.x); ffma2(acc2[0][7], qd0, pD.y);
            ffma2(acc2[1][0], qd1, pA.x); ffma2(acc2[1][1], qd1, pA.y);
            ffma2(acc2[1][2], qd1, pB.x); ffma2(acc2[1][3], qd1, pB.y);
            ffma2(acc2[1][4], qd1, pC.x); ffma2(acc2[1][5], qd1, pC.y);
            ffma2(acc2[1][6], qd1, pD.x); ffma2(acc2[1][7], qd1, pD.y);
            ffma2(acc2[2][0], qd2, pA.x); ffma2(acc2[2][1], qd2, pA.y);
            ffma2(acc2[2][2], qd2, pB.x); ffma2(acc2[2][3], qd2, pB.y);
            ffma2(acc2[2][4], qd2, pC.x); ffma2(acc2[2][5], qd2, pC.y);
            ffma2(acc2[2][6], qd2, pD.x); ffma2(acc2[2][7], qd2, pD.y);
            ffma2(acc2[3][0], qd3, pA.x); ffma2(acc2[3][1], qd3, pA.y);
            ffma2(acc2[3][2], qd3, pB.x); ffma2(acc2[3][3], qd3, pB.y);
            ffma2(acc2[3][4], qd3, pC.x); ffma2(acc2[3][5], qd3, pC.y);
            ffma2(acc2[3][6], qd3, pD.x); ffma2(acc2[3][7], qd3, pD.y);
        }
        __syncthreads();
    }

    // ---- epilogue (FTZ chain; n(j) = (j>>2)*128 + lane*4 + (j&3)) ----
    #pragma unroll 1
    for (int i = 0; i < 4; i++) {
        float av[16];
        #pragma unroll
        for (int m = 0; m < 8; m++) unpack2(acc2[i][m], av[2 * m], av[2 * m + 1]);

        float dmax = av[0];
        #pragma unroll
        for (int j = 1; j < 16; j++) dmax = fmaxf(dmax, av[j]);
        dmax = warp_maxf(dmax);
        float Xf = __fdiv_rn(dmax, 0.1f);

        double zs = 0.0;
        #pragma unroll
        for (int j = 0; j < 16; j++) {
            if (av[j] > dmax - 8.8f) {
                float x = __fdiv_rn(av[j], 0.1f);
                float e = expf(__fsub_rn(x, Xf));
                if (e >= FMINF) zs += (double)e;
            }
        }
        zs = warp_sumd(zs);
        float Za = (float)zs;

        float key[16];
        float kmax = -INFINITY;
        #pragma unroll
        for (int j = 0; j < 16; j++) {
            int n = ((j >> 2) * 128) + (lane * 4) + (j & 3);
            key[j] = fmaf(av[j] - dmax, 10.0f, tS[n]);
            kmax = fmaxf(kmax, key[j]);
        }
        kmax = warp_maxf(kmax);

        int bn = 0;
        float bp = 0.f;
        float bd = __shfl_sync(0xffffffffu, av[0], 0);   // dot(n=0) fallback

        if (kmax >= -87.4f) {
            float thr = kmax - 0.02f;
            #pragma unroll
            for (int j = 0; j < 16; j++) {
                unsigned msk = __ballot_sync(0xffffffffu, key[j] >= thr);
                while (msk) {
                    int ln = __ffs(msk) - 1;
                    msk &= msk - 1;
                    int n = ((j >> 2) * 128) + (ln * 4) + (j & 3);
                    float Ac = __shfl_sync(0xffffffffu, av[j], ln);
                    float x = __fdiv_rn(Ac, 0.1f);
                    float e = expf(__fsub_rn(x, Xf));
                    if (e < FMINF) e = 0.f;
                    float s = __fdiv_rn(e, Za);
                    if (s < FMINF) s = 0.f;
                    float p = __fmul_rn(s, wS[n]);
                    if (p < FMINF) p = 0.f;
                    // argmax with first-(smallest)-index tie rule
                    if (p > bp || (p == bp && p > 0.f && n < bn)) {
                        bp = p; bn = n; bd = Ac;
                    }
                }
            }
        }

        if (lane == 0) {
            int l = l0 + lg * 4 + i;
            float rd = fmaf(-2.0f, bd, g_qq[(size_t)b * LL + l]) + pn2S[bn];
            out[(size_t)b * LL + l] = rd;
        }
    }
}

// ---------------------------------------------------------------------------
extern "C" void kernel_launch(void* const* d_in, const int* in_sizes, int n_in,
                              void* d_out, int out_size) {
    const float* Q = nullptr;
    const float* P = nullptr;
    const float* G = nullptr;
    for (int i = 0; i < n_in; i++) {
        if (in_sizes[i] == BB * LL * CCH) Q = (const float*)d_in[i];
        else if (in_sizes[i] == NN * CCH) P = (const float*)d_in[i];
        else if (in_sizes[i] == BB * KK * CCH) G = (const float*)d_in[i];
    }
    float* out = (float*)d_out;

    prep_w_kernel<<<BB, 256>>>(P, G);
    prep_pn2_kernel<<<NN / 8, 256>>>(P);
    prep_qq_kernel<<<BB * LL / 8, 256>>>(Q);
    dim3 grid(LL / 32, BB);
    match_kernel<<<grid, 256>>>(Q, P, out);
}